// round 2
// baseline (speedup 1.0000x reference)
#include <cuda_runtime.h>
#include <cstdint>

// Unpool (max_unpool_with_argmax inverse): out[mask[i]] = val[i], zeros elsewhere.
// Gather formulation: out[o] = (mask[src(o)] == o) ? val[src(o)] : 0
// Shapes fixed: val (16,64,64,128) f32, mask same count int32 (JAX x64 off),
// out (16,128,128,128) f32. All flat indices < 2^25, fit int32.

namespace {
constexpr int C  = 128;
constexpr int W2 = 128;   // W * 2
constexpr int H2 = 128;   // H * 2
constexpr int OUT_ELEMS = 16 * 128 * 128 * 128;  // 33,554,432 (< 2^31)
}

__global__ __launch_bounds__(256) void unpool_gather_kernel(
    const float4* __restrict__ val4,     // val as float4
    const int4*   __restrict__ mask4,    // mask as int32x4
    float4*       __restrict__ out4)     // out as float4
{
    // One thread = 4 consecutive output channels. One warp = one full
    // (b, h2, w2) channel row of 128 floats -> fully coalesced 512B store,
    // 512B val load, 512B mask load.
    const int t = blockIdx.x * blockDim.x + threadIdx.x;   // < 2^23
    const int o = t << 2;                                  // flat output idx, < 2^25

    const int c  = o & (C - 1);            // bits [0,7)
    const int w2 = (o >> 7)  & (W2 - 1);
    const int h2 = (o >> 14) & (H2 - 1);
    const int b  = o >> 21;

    // Source (unpooled) position: ((b*64 + h2/2)*64 + w2/2)*128 + c
    const int in_idx = ((((b << 6) + (h2 >> 1)) << 6) + (w2 >> 1)) * C + c;

    const float4 v = val4 [in_idx >> 2];
    const int4   m = mask4[in_idx >> 2];

    float4 r;
    r.x = (m.x == o    ) ? v.x : 0.0f;
    r.y = (m.y == o + 1) ? v.y : 0.0f;
    r.z = (m.z == o + 2) ? v.z : 0.0f;
    r.w = (m.w == o + 3) ? v.w : 0.0f;

    out4[t] = r;
}

extern "C" void kernel_launch(void* const* d_in, const int* in_sizes, int n_in,
                              void* d_out, int out_size)
{
    const float4* val4  = (const float4*)d_in[0];
    const int4*   mask4 = (const int4*)d_in[1];
    float4*       out4  = (float4*)d_out;

    const int n_vec   = OUT_ELEMS >> 2;      // 8,388,608 threads
    const int threads = 256;
    const int blocks  = n_vec / threads;     // 32,768

    unpool_gather_kernel<<<blocks, threads>>>(val4, mask4, out4);
}

// round 4
// speedup vs baseline: 1.1617x; 1.1617x over previous
#include <cuda_runtime.h>
#include <cstdint>

// Unpool (max_unpool_with_argmax inverse), gather formulation, input-centric:
// one thread loads one val float4 + mask int4 (input pos b,h,w,c..c+3) and
// produces the four output float4s in the 2x2 window (2h+dh, 2w+dw).
// out[o] = (mask == o) ? val : 0. Mask is int32 (JAX x64 disabled).
//
// Shapes: val (16,64,64,128) f32, mask same int32, out (16,128,128,128) f32.

namespace {
constexpr int C  = 128;
constexpr int IN_ELEMS = 16 * 64 * 64 * 128;   // 8,388,608
}

__global__ __launch_bounds__(256) void unpool_scatter4_kernel(
    const float4* __restrict__ val4,
    const int4*   __restrict__ mask4,
    float4*       __restrict__ out4)
{
    const int t = blockIdx.x * blockDim.x + threadIdx.x;   // < 2^21
    const int i = t << 2;                                  // flat input elem idx

    const int c = i & (C - 1);          // bits [0,7)
    const int w = (i >> 7)  & 63;
    const int h = (i >> 13) & 63;
    const int b = i >> 19;

    const float4 v = __ldg(&val4[t]);
    const int4   m = __ldg(&mask4[t]);

    // Output row base for (h2, w2): ((b*128 + h2)*128 + w2)*128 + c
    const int h2 = h << 1;
    const int w2 = w << 1;
    const int base00 = ((((b << 7) + h2) << 7) + w2) << 7;  // c added below

    // The four candidate output flat indices for component .x:
    //   o(dh,dw) = base00 + dh*(128*128) + dw*128 + c
    #pragma unroll
    for (int dh = 0; dh < 2; ++dh) {
        #pragma unroll
        for (int dw = 0; dw < 2; ++dw) {
            const int o = base00 + (dh << 14) + (dw << 7) + c;
            float4 r;
            r.x = (m.x == o    ) ? v.x : 0.0f;
            r.y = (m.y == o + 1) ? v.y : 0.0f;
            r.z = (m.z == o + 2) ? v.z : 0.0f;
            r.w = (m.w == o + 3) ? v.w : 0.0f;
            __stcs(&out4[o >> 2], r);    // streaming: don't evict inputs from L2
        }
    }
}

extern "C" void kernel_launch(void* const* d_in, const int* in_sizes, int n_in,
                              void* d_out, int out_size)
{
    const float4* val4  = (const float4*)d_in[0];
    const int4*   mask4 = (const int4*)d_in[1];
    float4*       out4  = (float4*)d_out;

    const int n_vec   = IN_ELEMS >> 2;       // 2,097,152 threads
    const int threads = 256;
    const int blocks  = n_vec / threads;     // 8192

    unpool_scatter4_kernel<<<blocks, threads>>>(val4, mask4, out4);
}